// round 4
// baseline (speedup 1.0000x reference)
#include <cuda_runtime.h>
#include <cuda_bf16.h>
#include <cstdint>

// ---------------- Problem constants ----------------
#define BATCH   16
#define CIN     32
#define WH_IN   224
#define WH_OUT  222
#define COUT    64
#define KSTEPS  18                       // 288 / 16
#define NROWS   (BATCH * WH_OUT)         // 3552 = 148 * 24
#define ROWS_PER_CTA 24
#define OPLANE  (BATCH * WH_OUT * WH_OUT)  // 788544

// ---------------- SMEM layout ----------------
// Input stage: 48 pair-rows (16 chan-pairs x 3 dy) x 248 u32 cols. hi then lo.
#define ASTRIDE 248                       // u32 per pair-row; 3*248 % 32 == 24 -> conflict-free
#define A_HI_BYTES (48 * ASTRIDE * 4)     // 47616
#define LOOFF      A_HI_BYTES
#define SM_A   0
#define SM_B   (2 * A_HI_BYTES)           // 95232
#define BSTRIDE_B 1168                    // bytes per n-row: 72 slots *16 + 16 pad
#define SMEM_BYTES (SM_B + COUT * BSTRIDE_B)   // 95232 + 74752 = 169984

// ---------------- helpers ----------------
static __device__ __forceinline__ uint32_t smem_u32(const void* p) {
    uint32_t a;
    asm("{ .reg .u64 t; cvta.to.shared.u64 t, %1; cvt.u32.u64 %0, t; }" : "=r"(a) : "l"(p));
    return a;
}
static __device__ __forceinline__ uint32_t lds_u32(uint32_t a) {
    uint32_t v; asm volatile("ld.shared.b32 %0, [%1];" : "=r"(v) : "r"(a)); return v;
}
static __device__ __forceinline__ void lds_u128(uint32_t a, uint32_t* v) {
    asm volatile("ld.shared.v4.b32 {%0,%1,%2,%3}, [%4];"
                 : "=r"(v[0]), "=r"(v[1]), "=r"(v[2]), "=r"(v[3]) : "r"(a));
}
static __device__ __forceinline__ void sts_u128(uint32_t a, const uint32_t* v) {
    asm volatile("st.shared.v4.b32 [%0], {%1,%2,%3,%4};"
                 :: "r"(a), "r"(v[0]), "r"(v[1]), "r"(v[2]), "r"(v[3]));
}
// pack two f32 -> bf16x2: LOW = v0, HIGH = v1
static __device__ __forceinline__ uint32_t pack_bf16x2(float v0, float v1) {
    uint32_t w;
    asm("cvt.rn.bf16x2.f32 %0, %1, %2;" : "=r"(w) : "f"(v1), "f"(v0));
    return w;
}
static __device__ __forceinline__ void split2(float v0, float v1, uint32_t& hi, uint32_t& lo) {
    hi = pack_bf16x2(v0, v1);
    const float h0 = __uint_as_float(hi << 16);
    const float h1 = __uint_as_float(hi & 0xFFFF0000u);
    lo = pack_bf16x2(v0 - h0, v1 - h1);
}
static __device__ __forceinline__ void mma_bf16(float* d, const uint32_t* a,
                                                uint32_t b0, uint32_t b1) {
    asm volatile(
        "mma.sync.aligned.m16n8k16.row.col.f32.bf16.bf16.f32 "
        "{%0,%1,%2,%3}, {%4,%5,%6,%7}, {%8,%9}, {%0,%1,%2,%3};"
        : "+f"(d[0]), "+f"(d[1]), "+f"(d[2]), "+f"(d[3])
        : "r"(a[0]), "r"(a[1]), "r"(a[2]), "r"(a[3]), "r"(b0), "r"(b1));
}

__global__ void __launch_bounds__(256, 1)
quanv_mma2_kernel(const float* __restrict__ x, const float* __restrict__ w,
                  float* __restrict__ out)
{
    extern __shared__ char smem[];
    const uint32_t sbase = smem_u32(smem);
    const uint32_t a_hi  = sbase + SM_A;
    const uint32_t b_sm  = sbase + SM_B;

    const int tid   = threadIdx.x;
    const int wid   = tid >> 5;
    const int lid   = tid & 31;
    const int r     = lid >> 2;
    const int q     = lid & 3;
    const int wx    = wid >> 1;     // 0..3 : M-quarter (64 px)
    const int nhalf = wid & 1;      // 0..1 : N-half (32 ch)

    // ---- one-time: build B (hi/lo interleaved v4) ----
    // slot (n, ks, q) holds {bh(pair h=0), bh(h=1), bl(h=0), bl(h=1)}
    // logical k of hw-pair (q, h): channels c = 2*(chalf*8 + q + 4h) + {0,1}, tap = ks%9
    #pragma unroll 1
    for (int u = tid; u < COUT * 72; u += 256) {
        const int n   = u / 72;
        const int rem = u - n * 72;
        const int ks  = rem >> 2;
        const int qq  = rem & 3;
        const int tap = ks % 9, ch = ks / 9;
        uint32_t bw[4];
        #pragma unroll
        for (int h = 0; h < 2; ++h) {
            const int c = 2 * (ch * 8 + qq + 4 * h);
            const float w0 = w[n * 288 + c * 9 + tap];
            const float w1 = w[n * 288 + (c + 1) * 9 + tap];
            split2(w0, w1, bw[h], bw[2 + h]);
        }
        sts_u128(b_sm + (uint32_t)(n * BSTRIDE_B + rem * 16), bw);
    }

    // ---- per-thread constants ----
    // A base addresses: tile j, row-half h -> col = min(px,221); +3q pair-rows
    uint32_t abase[4][2];
    #pragma unroll
    for (int j = 0; j < 4; ++j)
        #pragma unroll
        for (int h = 0; h < 2; ++h) {
            int px = wx * 64 + j * 16 + r + 8 * h;
            int col = px < 222 ? px : 221;
            abase[j][h] = a_hi + (uint32_t)((3 * q) * ASTRIDE + col) * 4;
        }
    const uint32_t bb = b_sm + (uint32_t)((nhalf * 32 + r) * BSTRIDE_B + q * 16);

    const int t0 = blockIdx.x * ROWS_PER_CTA;

    #pragma unroll 1
    for (int it = 0; it < ROWS_PER_CTA; ++it) {
        const int t = t0 + it;
        const int b = t / WH_OUT;
        const int y = t - b * WH_OUT;

        __syncthreads();   // previous compute done reading smem

        // ---- stage: 48 pair-rows x 224 cols, split into bf16 hi/lo pairs ----
        #pragma unroll 1
        for (int u = tid; u < 48 * 56; u += 256) {
            const int pr = u / 56;
            const int cq = u - pr * 56;
            const int c2 = pr / 3;
            const int dy = pr - c2 * 3;
            const float* g = x + (((size_t)(b * CIN + 2 * c2) * WH_IN) + (y + dy)) * WH_IN + cq * 4;
            const float4 f0 = *(const float4*)g;
            const float4 f1 = *(const float4*)(g + WH_IN * WH_IN);
            uint32_t hi[4], lo[4];
            split2(f0.x, f1.x, hi[0], lo[0]);
            split2(f0.y, f1.y, hi[1], lo[1]);
            split2(f0.z, f1.z, hi[2], lo[2]);
            split2(f0.w, f1.w, hi[3], lo[3]);
            const uint32_t da = a_hi + (uint32_t)(pr * ASTRIDE + cq * 4) * 4;
            sts_u128(da, hi);
            sts_u128(da + LOOFF, lo);
        }
        __syncthreads();

        // ---- compute ----
        float acc[4][4][4];
        #pragma unroll
        for (int j = 0; j < 4; ++j)
            #pragma unroll
            for (int nb = 0; nb < 4; ++nb)
                #pragma unroll
                for (int e = 0; e < 4; ++e) acc[j][nb][e] = 0.0f;

        #pragma unroll
        for (int ks = 0; ks < KSTEPS; ++ks) {
            const int tap = ks % 9, ch = ks / 9;
            const uint32_t off = (uint32_t)(((ch * 24 + tap / 3) * ASTRIDE + (tap % 3)) * 4);
            uint32_t ahi[4][4], alo[4][4];
            #pragma unroll
            for (int j = 0; j < 4; ++j) {
                ahi[j][0] = lds_u32(abase[j][0] + off);
                ahi[j][1] = lds_u32(abase[j][1] + off);
                ahi[j][2] = lds_u32(abase[j][0] + off + 12 * ASTRIDE * 4);
                ahi[j][3] = lds_u32(abase[j][1] + off + 12 * ASTRIDE * 4);
                alo[j][0] = lds_u32(abase[j][0] + off + LOOFF);
                alo[j][1] = lds_u32(abase[j][1] + off + LOOFF);
                alo[j][2] = lds_u32(abase[j][0] + off + LOOFF + 12 * ASTRIDE * 4);
                alo[j][3] = lds_u32(abase[j][1] + off + LOOFF + 12 * ASTRIDE * 4);
            }
            #pragma unroll
            for (int nb = 0; nb < 4; ++nb) {
                uint32_t bq[4];
                lds_u128(bb + (uint32_t)(nb * 8 * BSTRIDE_B + ks * 64), bq);
                #pragma unroll
                for (int j = 0; j < 4; ++j) {
                    mma_bf16(acc[j][nb], ahi[j], bq[0], bq[1]);
                    mma_bf16(acc[j][nb], ahi[j], bq[2], bq[3]);
                    mma_bf16(acc[j][nb], alo[j], bq[0], bq[1]);
                }
            }
        }

        // ---- store ----
        const size_t rowbase = ((size_t)b * WH_OUT + y) * WH_OUT;
        float* ob = out + rowbase + (size_t)(nhalf * 32 + 2 * q) * OPLANE;
        #pragma unroll
        for (int j = 0; j < 4; ++j)
            #pragma unroll
            for (int h = 0; h < 2; ++h) {
                const int px = wx * 64 + j * 16 + r + 8 * h;
                if (px < WH_OUT) {
                    #pragma unroll
                    for (int nb = 0; nb < 4; ++nb) {
                        ob[(size_t)(nb * 8) * OPLANE + px]     = acc[j][nb][2 * h];
                        ob[(size_t)(nb * 8 + 1) * OPLANE + px] = acc[j][nb][2 * h + 1];
                    }
                }
            }
    }
}

extern "C" void kernel_launch(void* const* d_in, const int* in_sizes, int n_in,
                              void* d_out, int out_size)
{
    const float* x = (const float*)d_in[0];
    const float* w = (const float*)d_in[1];
    float* out = (float*)d_out;

    static bool attr_set = false;
    if (!attr_set) {
        cudaFuncSetAttribute(quanv_mma2_kernel,
                             cudaFuncAttributeMaxDynamicSharedMemorySize, SMEM_BYTES);
        attr_set = true;
    }
    quanv_mma2_kernel<<<148, 256, SMEM_BYTES>>>(x, w, out);
}

// round 5
// speedup vs baseline: 1.0454x; 1.0454x over previous
#include <cuda_runtime.h>
#include <cuda_bf16.h>
#include <cstdint>

// ---------------- Problem constants ----------------
#define BATCH   16
#define CIN     32
#define WH_IN   224
#define WH_OUT  222
#define COUT    64
#define KSTEPS  18
#define NTILES  (BATCH * WH_OUT * 2)     // 7104 = 148*48
#define TILES_PER_CTA 48
#define OPLANE  (BATCH * WH_OUT * WH_OUT)

// ---------------- SMEM layout ----------------
// A stage (per buffer): 48 pair-rows x 152 u32 cols (132 used), hi then lo.
// 3*152 = 456 == 8 (mod 32) -> A LDS banks = 8q + r, conflict-free.
#define AST        152
#define A_HALF     (48 * AST * 4)        // 29184 (hi)
#define LOOFF      A_HALF
#define ABUF       (2 * A_HALF)          // 58368 per buffer
#define SM_B       (2 * ABUF)            // 116736
#define BSTRIDE_B  1168                  // bytes per n-row (72 slots*16 + pad)
#define SMEM_BYTES (SM_B + COUT * BSTRIDE_B)   // 191488

// ---------------- helpers ----------------
static __device__ __forceinline__ uint32_t smem_u32(const void* p) {
    uint32_t a;
    asm("{ .reg .u64 t; cvta.to.shared.u64 t, %1; cvt.u32.u64 %0, t; }" : "=r"(a) : "l"(p));
    return a;
}
static __device__ __forceinline__ uint32_t lds_u32(uint32_t a) {
    uint32_t v; asm volatile("ld.shared.b32 %0, [%1];" : "=r"(v) : "r"(a)); return v;
}
static __device__ __forceinline__ void lds_u128(uint32_t a, uint32_t* v) {
    asm volatile("ld.shared.v4.b32 {%0,%1,%2,%3}, [%4];"
                 : "=r"(v[0]), "=r"(v[1]), "=r"(v[2]), "=r"(v[3]) : "r"(a));
}
static __device__ __forceinline__ void sts_u128(uint32_t a, const uint32_t* v) {
    asm volatile("st.shared.v4.b32 [%0], {%1,%2,%3,%4};"
                 :: "r"(a), "r"(v[0]), "r"(v[1]), "r"(v[2]), "r"(v[3]));
}
static __device__ __forceinline__ uint32_t pack_bf16x2(float v0, float v1) {
    uint32_t w;
    asm("cvt.rn.bf16x2.f32 %0, %1, %2;" : "=r"(w) : "f"(v1), "f"(v0));
    return w;
}
static __device__ __forceinline__ void split2(float v0, float v1, uint32_t& hi, uint32_t& lo) {
    hi = pack_bf16x2(v0, v1);
    const float h0 = __uint_as_float(hi << 16);
    const float h1 = __uint_as_float(hi & 0xFFFF0000u);
    lo = pack_bf16x2(v0 - h0, v1 - h1);
}
static __device__ __forceinline__ void mma_bf16(float* d, const uint32_t* a,
                                                uint32_t b0, uint32_t b1) {
    asm volatile(
        "mma.sync.aligned.m16n8k16.row.col.f32.bf16.bf16.f32 "
        "{%0,%1,%2,%3}, {%4,%5,%6,%7}, {%8,%9}, {%0,%1,%2,%3};"
        : "+f"(d[0]), "+f"(d[1]), "+f"(d[2]), "+f"(d[3])
        : "r"(a[0]), "r"(a[1]), "r"(a[2]), "r"(a[3]), "r"(b0), "r"(b1));
}

#define BAR_SYNC(id)   asm volatile("bar.sync %0, %1;"   :: "r"(id), "r"(384) : "memory")
#define BAR_ARRIVE(id) asm volatile("bar.arrive %0, %1;" :: "r"(id), "r"(384) : "memory")
#define MEMBAR_CTA()   asm volatile("membar.cta;" ::: "memory")

__global__ void __launch_bounds__(384, 1)
quanv_ws_kernel(const float* __restrict__ x, const float* __restrict__ w,
                float* __restrict__ out)
{
    extern __shared__ char smem[];
    const uint32_t sbase = smem_u32(smem);
    const uint32_t a_sm  = sbase;
    const uint32_t b_sm  = sbase + SM_B;

    const int tid = threadIdx.x;
    const int wid = tid >> 5;
    const int lid = tid & 31;
    const int t0  = blockIdx.x * TILES_PER_CTA;

    // ---- one-time: build B (hi/lo interleaved v4), all 384 threads ----
    // slot (n, ks, q): {bh(h0), bh(h1), bl(h0), bl(h1)};
    // channels c = 2*(ch*8 + q + 4h) + {0,1}, tap = ks%9, ch = ks/9
    #pragma unroll 1
    for (int u = tid; u < COUT * 72; u += 384) {
        const int n   = u / 72;
        const int rem = u - n * 72;
        const int ks  = rem >> 2;
        const int qq  = rem & 3;
        const int tap = ks % 9, ch = ks / 9;
        uint32_t bw[4];
        #pragma unroll
        for (int h = 0; h < 2; ++h) {
            const int c = 2 * (ch * 8 + qq + 4 * h);
            split2(w[n * 288 + c * 9 + tap], w[n * 288 + (c + 1) * 9 + tap],
                   bw[h], bw[2 + h]);
        }
        sts_u128(b_sm + (uint32_t)(n * BSTRIDE_B + rem * 16), bw);
    }
    __syncthreads();

    if (wid < 8) {
        // ================= CONSUMERS: 8 warps, M32 x N32 each =================
        const int r = lid >> 2, q = lid & 3;
        const int wx = wid >> 1;          // 0..3 -> 32-px slice
        const int nhalf = wid & 1;        // 0..1 -> 32-ch half
        const uint32_t bb = b_sm + (uint32_t)((nhalf * 32 + r) * BSTRIDE_B + q * 16);

        #pragma unroll 1
        for (int it = 0; it < TILES_PER_CTA; ++it) {
            const int t    = t0 + it;
            const int b    = t / (WH_OUT * 2);
            const int rr   = t - b * (WH_OUT * 2);
            const int y    = rr >> 1;
            const int half = rr & 1;
            const int x0   = half ? 94 : 0;
            const int xoff = half ? 2 : 0;

            BAR_SYNC(1 + (it & 1));       // buffer filled
            const uint32_t abuf = a_sm + (uint32_t)((it & 1) * ABUF);

            uint32_t ab[2][2];
            #pragma unroll
            for (int j = 0; j < 2; ++j)
                #pragma unroll
                for (int h = 0; h < 2; ++h)
                    ab[j][h] = abuf + (uint32_t)((3 * q) * AST + xoff
                               + wx * 32 + j * 16 + r + 8 * h) * 4;

            float acc[2][4][4];
            #pragma unroll
            for (int j = 0; j < 2; ++j)
                #pragma unroll
                for (int nb = 0; nb < 4; ++nb)
                    #pragma unroll
                    for (int e = 0; e < 4; ++e) acc[j][nb][e] = 0.0f;

            #pragma unroll
            for (int ks = 0; ks < KSTEPS; ++ks) {
                const int tap = ks % 9, ch = ks / 9;
                const uint32_t off = (uint32_t)(((ch * 24 + tap / 3) * AST + (tap % 3)) * 4);
                uint32_t ahi[2][4], alo[2][4];
                #pragma unroll
                for (int j = 0; j < 2; ++j) {
                    ahi[j][0] = lds_u32(ab[j][0] + off);
                    ahi[j][1] = lds_u32(ab[j][1] + off);
                    ahi[j][2] = lds_u32(ab[j][0] + off + 12 * AST * 4);
                    ahi[j][3] = lds_u32(ab[j][1] + off + 12 * AST * 4);
                    alo[j][0] = lds_u32(ab[j][0] + off + LOOFF);
                    alo[j][1] = lds_u32(ab[j][1] + off + LOOFF);
                    alo[j][2] = lds_u32(ab[j][0] + off + LOOFF + 12 * AST * 4);
                    alo[j][3] = lds_u32(ab[j][1] + off + LOOFF + 12 * AST * 4);
                }
                #pragma unroll
                for (int nb = 0; nb < 4; ++nb) {
                    uint32_t bq[4];
                    lds_u128(bb + (uint32_t)(nb * 8 * BSTRIDE_B + ks * 64), bq);
                    #pragma unroll
                    for (int j = 0; j < 2; ++j) {
                        mma_bf16(acc[j][nb], ahi[j], bq[0], bq[1]);
                        mma_bf16(acc[j][nb], ahi[j], bq[2], bq[3]);
                        mma_bf16(acc[j][nb], alo[j], bq[0], bq[1]);
                    }
                }
            }

            BAR_ARRIVE(3 + (it & 1));     // buffer consumed (stores use regs only)

            float* ob = out + ((size_t)b * WH_OUT + y) * WH_OUT
                            + (size_t)(nhalf * 32 + 2 * q) * OPLANE;
            #pragma unroll
            for (int j = 0; j < 2; ++j)
                #pragma unroll
                for (int h = 0; h < 2; ++h) {
                    const int px = x0 + wx * 32 + j * 16 + r + 8 * h;
                    #pragma unroll
                    for (int nb = 0; nb < 4; ++nb) {
                        ob[(size_t)(nb * 8) * OPLANE + px]     = acc[j][nb][2 * h];
                        ob[(size_t)(nb * 8 + 1) * OPLANE + px] = acc[j][nb][2 * h + 1];
                    }
                }
        }
    } else {
        // ================= PRODUCERS: 4 warps stage A =================
        const int ptid = tid - 256;       // 0..127
        #pragma unroll 1
        for (int it = 0; it < TILES_PER_CTA; ++it) {
            const int t  = t0 + it;
            const int b  = t / (WH_OUT * 2);
            const int rr = t - b * (WH_OUT * 2);
            const int y  = rr >> 1;
            const int xs = (rr & 1) ? 92 : 0;

            if (it >= 2) BAR_SYNC(3 + (it & 1));   // buffer free
            const uint32_t abuf = a_sm + (uint32_t)((it & 1) * ABUF);

            #pragma unroll 1
            for (int u = ptid; u < 48 * 33; u += 128) {
                const int pr = u / 33;
                const int cq = u - pr * 33;
                const int c2 = pr / 3;
                const int dy = pr - c2 * 3;
                const float* g = x + (((size_t)(b * CIN + 2 * c2) * WH_IN) + (y + dy)) * WH_IN
                                   + xs + cq * 4;
                const float4 f0 = *(const float4*)g;
                const float4 f1 = *(const float4*)(g + WH_IN * WH_IN);
                uint32_t hi[4], lo[4];
                split2(f0.x, f1.x, hi[0], lo[0]);
                split2(f0.y, f1.y, hi[1], lo[1]);
                split2(f0.z, f1.z, hi[2], lo[2]);
                split2(f0.w, f1.w, hi[3], lo[3]);
                const uint32_t da = abuf + (uint32_t)(pr * AST + cq * 4) * 4;
                sts_u128(da, hi);
                sts_u128(da + LOOFF, lo);
            }
            MEMBAR_CTA();
            BAR_ARRIVE(1 + (it & 1));     // buffer filled
        }
    }
}

extern "C" void kernel_launch(void* const* d_in, const int* in_sizes, int n_in,
                              void* d_out, int out_size)
{
    const float* x = (const float*)d_in[0];
    const float* w = (const float*)d_in[1];
    float* out = (float*)d_out;

    static bool attr_set = false;
    if (!attr_set) {
        cudaFuncSetAttribute(quanv_ws_kernel,
                             cudaFuncAttributeMaxDynamicSharedMemorySize, SMEM_BYTES);
        attr_set = true;
    }
    quanv_ws_kernel<<<148, 384, SMEM_BYTES>>>(x, w, out);
}

// round 6
// speedup vs baseline: 1.5566x; 1.4889x over previous
#include <cuda_runtime.h>
#include <cuda_fp16.h>
#include <cstdint>

// ---------------- Problem constants ----------------
#define BATCH   16
#define CIN     32
#define WH_IN   224
#define WH_OUT  222
#define COUT    64
#define KSTEPS  18
#define NTILES  (BATCH * WH_OUT * 2)     // 7104 = 148*48
#define TILES_PER_CTA 48
#define OPLANE  (BATCH * WH_OUT * WH_OUT)

// ---------------- SMEM layout ----------------
// A: ring of 4 y-row slots, each [16 chan-pairs][AST u32 cols] fp16x2 (hi only).
// AST = 136: q-stride 136 == 8 (mod 32) -> A LDS banks 8q+r, conflict-free; 136%4==0 -> STS.128 aligned.
#define AST        136
#define SLOT_BYTES (16 * AST * 4)        // 8704
#define A_BYTES    (4 * SLOT_BYTES)      // 34816
#define SM_B       A_BYTES
// B row stride: 304 words == 16 (mod 32) -> LDS.128 phases conflict-free.
#define BSTR       1216
#define SMEM_BYTES (SM_B + COUT * BSTR)  // 112640

// ---------------- helpers ----------------
static __device__ __forceinline__ uint32_t smem_u32(const void* p) {
    uint32_t a;
    asm("{ .reg .u64 t; cvta.to.shared.u64 t, %1; cvt.u32.u64 %0, t; }" : "=r"(a) : "l"(p));
    return a;
}
static __device__ __forceinline__ uint32_t lds_u32(uint32_t a) {
    uint32_t v; asm volatile("ld.shared.b32 %0, [%1];" : "=r"(v) : "r"(a)); return v;
}
static __device__ __forceinline__ void lds_u128(uint32_t a, uint32_t* v) {
    asm volatile("ld.shared.v4.b32 {%0,%1,%2,%3}, [%4];"
                 : "=r"(v[0]), "=r"(v[1]), "=r"(v[2]), "=r"(v[3]) : "r"(a));
}
static __device__ __forceinline__ void sts_u128(uint32_t a, const uint32_t* v) {
    asm volatile("st.shared.v4.b32 [%0], {%1,%2,%3,%4};"
                 :: "r"(a), "r"(v[0]), "r"(v[1]), "r"(v[2]), "r"(v[3]));
}
// pack two f32 -> f16x2 word: LOW half = v0, HIGH half = v1
static __device__ __forceinline__ uint32_t pack_f16x2(float v0, float v1) {
    uint32_t w;
    asm("cvt.rn.f16x2.f32 %0, %1, %2;" : "=r"(w) : "f"(v1), "f"(v0));
    return w;
}
static __device__ __forceinline__ void mma_f16(float* d, const uint32_t* a,
                                               uint32_t b0, uint32_t b1) {
    asm volatile(
        "mma.sync.aligned.m16n8k16.row.col.f32.f16.f16.f32 "
        "{%0,%1,%2,%3}, {%4,%5,%6,%7}, {%8,%9}, {%0,%1,%2,%3};"
        : "+f"(d[0]), "+f"(d[1]), "+f"(d[2]), "+f"(d[3])
        : "r"(a[0]), "r"(a[1]), "r"(a[2]), "r"(a[3]), "r"(b0), "r"(b1));
}

#define BAR_SYNC(id)   asm volatile("bar.sync %0, %1;"   :: "r"(id), "r"(384) : "memory")
#define BAR_ARRIVE(id) asm volatile("bar.arrive %0, %1;" :: "r"(id), "r"(384) : "memory")
#define MEMBAR_CTA()   asm volatile("membar.cta;" ::: "memory")

__global__ void __launch_bounds__(384, 1)
quanv_f16_kernel(const float* __restrict__ x, const float* __restrict__ w,
                 float* __restrict__ out)
{
    extern __shared__ char smem[];
    const uint32_t sbase = smem_u32(smem);
    const uint32_t a_sm  = sbase;
    const uint32_t b_sm  = sbase + SM_B;

    const int tid = threadIdx.x;
    const int wid = tid >> 5;
    const int lid = tid & 31;
    const int t0  = blockIdx.x * TILES_PER_CTA;

    // ---- one-time: build B = w split into fp16 hi/lo, v4 slots ----
    // slot (n, ks, qq): {bh(h0), bh(h1), bl(h0), bl(h1)};
    // channels c = 2*(ch*8 + qq + 4h) + {0,1}, tap = ks%9, ch = ks/9
    #pragma unroll 1
    for (int u = tid; u < COUT * 72; u += 384) {
        const int n   = u / 72;
        const int rem = u - n * 72;
        const int ks  = rem >> 2;
        const int qq  = rem & 3;
        const int tap = ks % 9, ch = ks / 9;
        uint32_t bw[4];
        #pragma unroll
        for (int h = 0; h < 2; ++h) {
            const int c = 2 * (ch * 8 + qq + 4 * h);
            const float w0 = w[n * 288 + c * 9 + tap];
            const float w1 = w[n * 288 + (c + 1) * 9 + tap];
            const uint32_t hw = pack_f16x2(w0, w1);
            const float h0 = __half2float(__ushort_as_half((unsigned short)(hw & 0xFFFFu)));
            const float h1 = __half2float(__ushort_as_half((unsigned short)(hw >> 16)));
            bw[h]     = hw;
            bw[2 + h] = pack_f16x2(w0 - h0, w1 - h1);
        }
        sts_u128(b_sm + (uint32_t)(n * BSTR + rem * 16), bw);
    }
    __syncthreads();

    if (wid < 8) {
        // ================= CONSUMERS: 8 warps, M32 x N32 =================
        const int r = lid >> 2, q = lid & 3;
        const int wx = wid >> 1;          // 0..3 -> 32-px slice
        const int nhalf = wid & 1;        // 0..1 -> 32-ch half
        const uint32_t bb = b_sm + (uint32_t)((nhalf * 32 + r) * BSTR + q * 16);

        // lane A base (without tile xoff / row-slot terms)
        uint32_t ab[2][2];
        #pragma unroll
        for (int j = 0; j < 2; ++j)
            #pragma unroll
            for (int h = 0; h < 2; ++h)
                ab[j][h] = a_sm + (uint32_t)(q * AST + wx * 32 + j * 16 + r + 8 * h) * 4;

        #pragma unroll 1
        for (int it = 0; it < TILES_PER_CTA; ++it) {
            const int t    = t0 + it;
            const int g    = t / WH_OUT;
            const int y    = t - g * WH_OUT;
            const int b    = g >> 1;
            const int half = g & 1;
            const int x0   = half ? 94 : 0;
            const int xoff = half ? 2 : 0;

            if (y == 0 && it > 0) BAR_SYNC(5);   // boundary rendezvous
            BAR_SYNC(1 + (it & 1));              // buffer filled

            uint32_t sl[3];
            #pragma unroll
            for (int d = 0; d < 3; ++d) sl[d] = (uint32_t)(((y + d) & 3) * SLOT_BYTES) + (uint32_t)(xoff * 4);

            float acc[2][4][4];
            #pragma unroll
            for (int j = 0; j < 2; ++j)
                #pragma unroll
                for (int nb = 0; nb < 4; ++nb)
                    #pragma unroll
                    for (int e = 0; e < 4; ++e) acc[j][nb][e] = 0.0f;

            #pragma unroll
            for (int ks = 0; ks < KSTEPS; ++ks) {
                const int tap = ks % 9, ch = ks / 9;
                const uint32_t off = sl[tap / 3] + (uint32_t)(ch * 8 * AST * 4 + (tap % 3) * 4);
                uint32_t ahi[2][4];
                #pragma unroll
                for (int j = 0; j < 2; ++j) {
                    ahi[j][0] = lds_u32(ab[j][0] + off);
                    ahi[j][1] = lds_u32(ab[j][1] + off);
                    ahi[j][2] = lds_u32(ab[j][0] + off + 4 * AST * 4);
                    ahi[j][3] = lds_u32(ab[j][1] + off + 4 * AST * 4);
                }
                #pragma unroll
                for (int nb = 0; nb < 4; ++nb) {
                    uint32_t bq[4];
                    lds_u128(bb + (uint32_t)(nb * 8 * BSTR + ks * 64), bq);
                    #pragma unroll
                    for (int j = 0; j < 2; ++j) {
                        mma_f16(acc[j][nb], ahi[j], bq[0], bq[1]);   // x * Wh
                        mma_f16(acc[j][nb], ahi[j], bq[2], bq[3]);   // x * Wl
                    }
                }
            }

            BAR_ARRIVE(3 + (it & 1));            // smem reads done

            float* ob = out + ((size_t)b * WH_OUT + y) * WH_OUT
                            + (size_t)(nhalf * 32 + 2 * q) * OPLANE;
            #pragma unroll
            for (int j = 0; j < 2; ++j)
                #pragma unroll
                for (int h = 0; h < 2; ++h) {
                    const int px = x0 + wx * 32 + j * 16 + r + 8 * h;
                    #pragma unroll
                    for (int nb = 0; nb < 4; ++nb) {
                        ob[(size_t)(nb * 8) * OPLANE + px]     = acc[j][nb][2 * h];
                        ob[(size_t)(nb * 8 + 1) * OPLANE + px] = acc[j][nb][2 * h + 1];
                    }
                }
        }
    } else {
        // ================= PRODUCERS: 4 warps, rolling 1-row stage =================
        const int ptid = tid - 256;       // 0..127
        #pragma unroll 1
        for (int it = 0; it < TILES_PER_CTA; ++it) {
            const int t    = t0 + it;
            const int g    = t / WH_OUT;
            const int y    = t - g * WH_OUT;
            const int b    = g >> 1;
            const int xs   = (g & 1) ? 92 : 0;

            if (it >= 2) BAR_SYNC(3 + (it & 1));      // ring slot free
            if (y == 0 && it > 0) BAR_SYNC(5);        // boundary rendezvous

            const int nrows = (it == 0 || y == 0) ? 3 : 1;
            const int yb    = (nrows == 3) ? y : (y + 2);

            #pragma unroll 1
            for (int u = ptid; u < nrows * 528; u += 128) {
                const int rrow = u / 528;
                const int v    = u - rrow * 528;
                const int c2   = v / 33;
                const int q4   = v - c2 * 33;
                const int yr   = yb + rrow;
                const float* gp = x + ((size_t)(b * CIN + 2 * c2) * WH_IN + yr) * WH_IN + xs + q4 * 4;
                const float4 f0 = *(const float4*)gp;
                const float4 f1 = *(const float4*)(gp + WH_IN * WH_IN);
                uint32_t hv[4];
                hv[0] = pack_f16x2(f0.x, f1.x);
                hv[1] = pack_f16x2(f0.y, f1.y);
                hv[2] = pack_f16x2(f0.z, f1.z);
                hv[3] = pack_f16x2(f0.w, f1.w);
                sts_u128(a_sm + (uint32_t)((yr & 3) * SLOT_BYTES)
                              + (uint32_t)((c2 * AST + q4 * 4) * 4), hv);
            }
            MEMBAR_CTA();
            BAR_ARRIVE(1 + (it & 1));                 // buffer filled
        }
    }
}

extern "C" void kernel_launch(void* const* d_in, const int* in_sizes, int n_in,
                              void* d_out, int out_size)
{
    const float* x = (const float*)d_in[0];
    const float* w = (const float*)d_in[1];
    float* out = (float*)d_out;

    static bool attr_set = false;
    if (!attr_set) {
        cudaFuncSetAttribute(quanv_f16_kernel,
                             cudaFuncAttributeMaxDynamicSharedMemorySize, SMEM_BYTES);
        attr_set = true;
    }
    quanv_f16_kernel<<<148, 384, SMEM_BYTES>>>(x, w, out);
}